// round 1
// baseline (speedup 1.0000x reference)
#include <cuda_runtime.h>
#include <math.h>

#define BB 64
#define SS 2048
#define HH 128
#define MM (BB*SS)   // 131072

// Scratch (no cudaMalloc allowed): xi = x@Wi + b, and h history.
__device__ float g_xi[BB * SS * HH];
__device__ float g_h [BB * SS * HH];

// ---------------------------------------------------------------------------
// Generic GEMM for K=128, N=128:  C[M,128] = A[M,128] @ W[128,128] + bias[128]
// Tile: 64 rows x 128 cols per CTA, 256 threads, full K resident in shared.
// ---------------------------------------------------------------------------
__global__ __launch_bounds__(256) void gemm_k128(const float* __restrict__ A,
                                                 const float* __restrict__ W,
                                                 const float* __restrict__ bias,
                                                 float* __restrict__ C) {
    extern __shared__ float smem[];
    float* sW = smem;              // 128*128 floats, no pad
    float* sA = smem + 128 * 128;  // 64 rows, pitch 132 (pad kills bank conflicts)

    const int tid  = threadIdx.x;
    const int row0 = blockIdx.x * 64;

    // Load W (128x128) into shared, vectorized.
    {
        const float4* Wg  = (const float4*)W;
        float4*       sW4 = (float4*)sW;
#pragma unroll
        for (int i = 0; i < 16; i++)
            sW4[tid + i * 256] = Wg[tid + i * 256];
    }
    // Load A tile (64x128) into shared with pitch 132.
    {
        const float4* Ag = (const float4*)(A + (size_t)row0 * 128);
#pragma unroll
        for (int i = 0; i < 8; i++) {
            int f4 = tid + i * 256;      // 0..2047
            int r  = f4 >> 5;            // row 0..63
            int c4 = f4 & 31;            // float4 col 0..31
            float4 v = Ag[f4];
            *(float4*)(sA + r * 132 + c4 * 4) = v;
        }
    }
    __syncthreads();

    const int tx = tid & 15;   // 16 column groups
    const int ty = tid >> 4;   // 16 row groups (4 rows each)

    float acc[4][8];
#pragma unroll
    for (int r = 0; r < 4; r++)
#pragma unroll
        for (int c = 0; c < 8; c++) acc[r][c] = 0.f;

#pragma unroll 4
    for (int k = 0; k < 128; k++) {
        float a0 = sA[(ty * 4 + 0) * 132 + k];
        float a1 = sA[(ty * 4 + 1) * 132 + k];
        float a2 = sA[(ty * 4 + 2) * 132 + k];
        float a3 = sA[(ty * 4 + 3) * 132 + k];
        float bv[8];
#pragma unroll
        for (int c = 0; c < 8; c++) bv[c] = sW[k * 128 + tx + 16 * c];
#pragma unroll
        for (int c = 0; c < 8; c++) {
            acc[0][c] = fmaf(a0, bv[c], acc[0][c]);
            acc[1][c] = fmaf(a1, bv[c], acc[1][c]);
            acc[2][c] = fmaf(a2, bv[c], acc[2][c]);
            acc[3][c] = fmaf(a3, bv[c], acc[3][c]);
        }
    }

#pragma unroll
    for (int c = 0; c < 8; c++) {
        float bv = bias[tx + 16 * c];
#pragma unroll
        for (int r = 0; r < 4; r++) {
            C[(size_t)(row0 + ty * 4 + r) * 128 + tx + 16 * c] = acc[r][c] + bv;
        }
    }
}

// ---------------------------------------------------------------------------
// Recurrence: one CTA per batch sequence. Thread j owns output column j and
// keeps Wh[:,j] in registers. h lives in shared (broadcast reads, float4).
// h_t = relu(tanh(xi_t + h_{t-1} @ Wh)); history written to g_h.
// ---------------------------------------------------------------------------
__global__ __launch_bounds__(128) void rnn_kernel(const float* __restrict__ Wh) {
    __shared__ __align__(16) float sh[HH];
    const int b = blockIdx.x;
    const int j = threadIdx.x;

    // Wh column j in registers (coalesced loads across threads).
    float w[HH];
#pragma unroll
    for (int k = 0; k < HH; k++) w[k] = Wh[k * HH + j];

    sh[j] = 0.f;
    const float* xip = g_xi + (size_t)b * SS * HH + j;
    float*       hp  = g_h  + (size_t)b * SS * HH + j;
    __syncthreads();

    float xi_cur = xip[0];
    for (int s = 0; s < SS; s++) {
        // Prefetch next step's xi (hides L2 latency behind the matvec).
        float xi_next = (s + 1 < SS) ? xip[(size_t)(s + 1) * HH] : 0.f;

        float a0 = xi_cur, a1 = 0.f, a2 = 0.f, a3 = 0.f;
        const float4* sh4 = (const float4*)sh;
#pragma unroll
        for (int k4 = 0; k4 < HH / 4; k4++) {
            float4 hv = sh4[k4];
            a0 = fmaf(hv.x, w[4 * k4 + 0], a0);
            a1 = fmaf(hv.y, w[4 * k4 + 1], a1);
            a2 = fmaf(hv.z, w[4 * k4 + 2], a2);
            a3 = fmaf(hv.w, w[4 * k4 + 3], a3);
        }
        float v  = (a0 + a1) + (a2 + a3);
        float hn = fmaxf(tanhf(v), 0.f);

        __syncthreads();             // all reads of old h done
        sh[j] = hn;
        hp[(size_t)s * HH] = hn;     // history for the output GEMM
        xi_cur = xi_next;
        __syncthreads();             // new h visible
    }
}

extern "C" void kernel_launch(void* const* d_in, const int* in_sizes, int n_in,
                              void* d_out, int out_size) {
    const float* x  = (const float*)d_in[0];
    const float* Wi = (const float*)d_in[1];
    const float* Wh = (const float*)d_in[2];
    const float* b  = (const float*)d_in[3];
    const float* Wo = (const float*)d_in[4];
    const float* bo = (const float*)d_in[5];
    float* y = (float*)d_out;

    float* xi_ptr = nullptr;
    float* h_ptr  = nullptr;
    cudaGetSymbolAddress((void**)&xi_ptr, g_xi);
    cudaGetSymbolAddress((void**)&h_ptr,  g_h);

    const size_t smem = (128 * 128 + 64 * 132) * sizeof(float);  // ~97 KB
    cudaFuncSetAttribute(gemm_k128, cudaFuncAttributeMaxDynamicSharedMemorySize,
                         (int)smem);

    // 1) xi = x @ Wi + b
    gemm_k128<<<MM / 64, 256, smem>>>(x, Wi, b, xi_ptr);
    // 2) sequential recurrence (parallel over batch)
    rnn_kernel<<<BB, 128>>>(Wh);
    // 3) y = h @ Wo + bo
    gemm_k128<<<MM / 64, 256, smem>>>(h_ptr, Wo, bo, y);
}

// round 2
// speedup vs baseline: 1.0012x; 1.0012x over previous
#include <cuda_runtime.h>
#include <math.h>

#define BB 64
#define SS 2048
#define HH 128
#define MM (BB*SS)   // 131072

// Scratch (no cudaMalloc allowed): xi = x@Wi + b, and h history.
__device__ float g_xi[BB * SS * HH];
__device__ float g_h [BB * SS * HH];

// ---------------------------------------------------------------------------
// Generic GEMM for K=128, N=128:  C[M,128] = A[M,128] @ W[128,128] + bias[128]
// Tile: 64 rows x 128 cols per CTA, 256 threads, full K resident in shared.
// ---------------------------------------------------------------------------
__global__ __launch_bounds__(256) void gemm_k128(const float* __restrict__ A,
                                                 const float* __restrict__ W,
                                                 const float* __restrict__ bias,
                                                 float* __restrict__ C) {
    extern __shared__ float smem[];
    float* sW = smem;              // 128*128 floats, no pad
    float* sA = smem + 128 * 128;  // 64 rows, pitch 132 (pad kills bank conflicts)

    const int tid  = threadIdx.x;
    const int row0 = blockIdx.x * 64;

    // Load W (128x128) into shared, vectorized.
    {
        const float4* Wg  = (const float4*)W;
        float4*       sW4 = (float4*)sW;
#pragma unroll
        for (int i = 0; i < 16; i++)
            sW4[tid + i * 256] = Wg[tid + i * 256];
    }
    // Load A tile (64x128) into shared with pitch 132.
    {
        const float4* Ag = (const float4*)(A + (size_t)row0 * 128);
#pragma unroll
        for (int i = 0; i < 8; i++) {
            int f4 = tid + i * 256;      // 0..2047
            int r  = f4 >> 5;            // row 0..63
            int c4 = f4 & 31;            // float4 col 0..31
            float4 v = Ag[f4];
            *(float4*)(sA + r * 132 + c4 * 4) = v;
        }
    }
    __syncthreads();

    const int tx = tid & 15;   // 16 column groups
    const int ty = tid >> 4;   // 16 row groups (4 rows each)

    float acc[4][8];
#pragma unroll
    for (int r = 0; r < 4; r++)
#pragma unroll
        for (int c = 0; c < 8; c++) acc[r][c] = 0.f;

#pragma unroll 4
    for (int k = 0; k < 128; k++) {
        float a0 = sA[(ty * 4 + 0) * 132 + k];
        float a1 = sA[(ty * 4 + 1) * 132 + k];
        float a2 = sA[(ty * 4 + 2) * 132 + k];
        float a3 = sA[(ty * 4 + 3) * 132 + k];
        float bv[8];
#pragma unroll
        for (int c = 0; c < 8; c++) bv[c] = sW[k * 128 + tx + 16 * c];
#pragma unroll
        for (int c = 0; c < 8; c++) {
            acc[0][c] = fmaf(a0, bv[c], acc[0][c]);
            acc[1][c] = fmaf(a1, bv[c], acc[1][c]);
            acc[2][c] = fmaf(a2, bv[c], acc[2][c]);
            acc[3][c] = fmaf(a3, bv[c], acc[3][c]);
        }
    }

#pragma unroll
    for (int c = 0; c < 8; c++) {
        float bv = bias[tx + 16 * c];
#pragma unroll
        for (int r = 0; r < 4; r++) {
            C[(size_t)(row0 + ty * 4 + r) * 128 + tx + 16 * c] = acc[r][c] + bv;
        }
    }
}

// ---------------------------------------------------------------------------
// Recurrence: one CTA per batch sequence. Thread j owns output column j and
// keeps Wh[:,j] in registers. h lives in shared (broadcast reads, float4).
// h_t = relu(tanh(xi_t + h_{t-1} @ Wh)); history written to g_h.
// ---------------------------------------------------------------------------
__global__ __launch_bounds__(128) void rnn_kernel(const float* __restrict__ Wh) {
    __shared__ __align__(16) float sh[HH];
    const int b = blockIdx.x;
    const int j = threadIdx.x;

    // Wh column j in registers (coalesced loads across threads).
    float w[HH];
#pragma unroll
    for (int k = 0; k < HH; k++) w[k] = Wh[k * HH + j];

    sh[j] = 0.f;
    const float* xip = g_xi + (size_t)b * SS * HH + j;
    float*       hp  = g_h  + (size_t)b * SS * HH + j;
    __syncthreads();

    float xi_cur = xip[0];
    for (int s = 0; s < SS; s++) {
        // Prefetch next step's xi (hides L2 latency behind the matvec).
        float xi_next = (s + 1 < SS) ? xip[(size_t)(s + 1) * HH] : 0.f;

        float a0 = xi_cur, a1 = 0.f, a2 = 0.f, a3 = 0.f;
        const float4* sh4 = (const float4*)sh;
#pragma unroll
        for (int k4 = 0; k4 < HH / 4; k4++) {
            float4 hv = sh4[k4];
            a0 = fmaf(hv.x, w[4 * k4 + 0], a0);
            a1 = fmaf(hv.y, w[4 * k4 + 1], a1);
            a2 = fmaf(hv.z, w[4 * k4 + 2], a2);
            a3 = fmaf(hv.w, w[4 * k4 + 3], a3);
        }
        float v  = (a0 + a1) + (a2 + a3);
        float hn = fmaxf(tanhf(v), 0.f);

        __syncthreads();             // all reads of old h done
        sh[j] = hn;
        hp[(size_t)s * HH] = hn;     // history for the output GEMM
        xi_cur = xi_next;
        __syncthreads();             // new h visible
    }
}

extern "C" void kernel_launch(void* const* d_in, const int* in_sizes, int n_in,
                              void* d_out, int out_size) {
    const float* x  = (const float*)d_in[0];
    const float* Wi = (const float*)d_in[1];
    const float* Wh = (const float*)d_in[2];
    const float* b  = (const float*)d_in[3];
    const float* Wo = (const float*)d_in[4];
    const float* bo = (const float*)d_in[5];
    float* y = (float*)d_out;

    float* xi_ptr = nullptr;
    float* h_ptr  = nullptr;
    cudaGetSymbolAddress((void**)&xi_ptr, g_xi);
    cudaGetSymbolAddress((void**)&h_ptr,  g_h);

    const size_t smem = (128 * 128 + 64 * 132) * sizeof(float);  // ~97 KB
    cudaFuncSetAttribute(gemm_k128, cudaFuncAttributeMaxDynamicSharedMemorySize,
                         (int)smem);

    // 1) xi = x @ Wi + b
    gemm_k128<<<MM / 64, 256, smem>>>(x, Wi, b, xi_ptr);
    // 2) sequential recurrence (parallel over batch)
    rnn_kernel<<<BB, 128>>>(Wh);
    // 3) y = h @ Wo + bo
    gemm_k128<<<MM / 64, 256, smem>>>(h_ptr, Wo, bo, y);
}